// round 8
// baseline (speedup 1.0000x reference)
#include <cuda_runtime.h>
#include <cuda_fp16.h>
#include <stdint.h>

// ---------------- problem constants ----------------
constexpr int B = 2, H = 16, S = 2048, D = 64;
constexpr int BH = B * H;
constexpr float INV_T = 1.0f / 32.0f;

constexpr int QT = 128;           // query rows per CTA
constexpr int NT = 64;            // keys per tile
constexpr int NTILES = S / NT;    // 32
constexpr int THREADS = 256;      // 8 warps, warp w owns q-rows 16w..16w+15

// smem: rows of 64 fp16 padded to 72 (144B) -> conflict-free ldmatrix
constexpr int RSB = 144;
constexpr int QTILE_B = 128 * RSB;   // 18432
constexpr int KTILE_B = 64 * RSB;    // 9216

constexpr int SM_Q    = 0;
constexpr int SM_K0   = SM_Q  + QTILE_B;     // 18432
constexpr int SM_K1   = SM_K0 + KTILE_B;     // 27648
constexpr int SM_V0   = SM_K1 + KTILE_B;     // 36864
constexpr int SM_V1   = SM_V0 + KTILE_B;     // 46080
constexpr int SM_MASK = SM_V1 + KTILE_B;     // 55296 (2048 floats)
constexpr int SM_INV  = SM_MASK + S * 4;     // 63488 (128 floats)
constexpr int SMEM_SZ = SM_INV + 512;        // 64000 B -> 3 CTAs/SM

// ---------------- device fp16 copies ----------------
__device__ __half g_q16[(size_t)BH * S * D];
__device__ __half g_k16[(size_t)BH * S * D];
__device__ __half g_v16[(size_t)BH * S * D];

// ---------------- helpers ----------------
__device__ __forceinline__ uint32_t su32(const void* p) {
    uint32_t a;
    asm("{ .reg .u64 t; cvta.to.shared.u64 t, %1; cvt.u32.u64 %0, t; }" : "=r"(a) : "l"(p));
    return a;
}
__device__ __forceinline__ void cpa16(uint32_t d, const void* s) {
    asm volatile("cp.async.cg.shared.global [%0], [%1], 16;" :: "r"(d), "l"(s));
}
#define CP_COMMIT() asm volatile("cp.async.commit_group;" ::: "memory")
#define CP_WAIT0()  asm volatile("cp.async.wait_group 0;" ::: "memory")

#define LDSM4(r0, r1, r2, r3, a) \
    asm volatile("ldmatrix.sync.aligned.m8n8.x4.shared.b16 {%0,%1,%2,%3}, [%4];" \
                 : "=r"(r0), "=r"(r1), "=r"(r2), "=r"(r3) : "r"(a))
#define LDSM4T(r0, r1, r2, r3, a) \
    asm volatile("ldmatrix.sync.aligned.m8n8.x4.trans.shared.b16 {%0,%1,%2,%3}, [%4];" \
                 : "=r"(r0), "=r"(r1), "=r"(r2), "=r"(r3) : "r"(a))

__device__ __forceinline__ void mma_f16(float4& c, uint32_t a0, uint32_t a1,
                                        uint32_t a2, uint32_t a3,
                                        uint32_t b0, uint32_t b1) {
    asm volatile(
        "mma.sync.aligned.m16n8k16.row.col.f32.f16.f16.f32 "
        "{%0,%1,%2,%3}, {%4,%5,%6,%7}, {%8,%9}, {%0,%1,%2,%3};"
        : "+f"(c.x), "+f"(c.y), "+f"(c.z), "+f"(c.w)
        : "r"(a0), "r"(a1), "r"(a2), "r"(a3), "r"(b0), "r"(b1));
}
__device__ __forceinline__ uint32_t packh2(float a, float b) {
    __half2 h = __floats2half2_rn(a, b);
    return *(uint32_t*)&h;
}
__device__ __forceinline__ float2 shfl_xor_f2(float2 v, int m) {
    v.x = __shfl_xor_sync(0xffffffffu, v.x, m);
    v.y = __shfl_xor_sync(0xffffffffu, v.y, m);
    return v;
}
// 4x4 transpose of float2 a[4] across a quad of lanes (q = lane&3).
__device__ __forceinline__ void quad_transpose_f2(float2 a[4], int q) {
    {
        float2 v = (q & 1) ? a[0] : a[1];
        v = shfl_xor_f2(v, 1);
        if (q & 1) a[0] = v; else a[1] = v;
        float2 u = (q & 1) ? a[2] : a[3];
        u = shfl_xor_f2(u, 1);
        if (q & 1) a[2] = u; else a[3] = u;
    }
    {
        float2 v = (q & 2) ? a[0] : a[2];
        v = shfl_xor_f2(v, 2);
        if (q & 2) a[0] = v; else a[2] = v;
        float2 u = (q & 2) ? a[1] : a[3];
        u = shfl_xor_f2(u, 2);
        if (q & 2) a[1] = u; else a[3] = u;
    }
}

// 128-row Q tile (1152 chunks / 256 thr -> 4.5, do 128 rows = 1024 chunks in 4)
__device__ __forceinline__ void load_q(uint32_t sdst, const __half* g, int tid) {
#pragma unroll
    for (int it = 0; it < 4; it++) {
        int f = tid + it * THREADS;          // 1024 chunks = 128 rows x 8
        int r = f >> 3, c = f & 7;
        cpa16(sdst + r * RSB + c * 16, g + r * 64 + c * 8);
    }
}
// 64-row K/V tile: 512 chunks / 256 threads = 2 each
__device__ __forceinline__ void load_t64(uint32_t sdst, const __half* g, int tid) {
#pragma unroll
    for (int it = 0; it < 2; it++) {
        int f = tid + it * THREADS;
        int r = f >> 3, c = f & 7;
        cpa16(sdst + r * RSB + c * 16, g + r * 64 + c * 8);
    }
}

// ---------------- prep: fp32 -> fp16 (Q scaled by 1/T) ----------------
__global__ void prep16(const float* __restrict__ q, const float* __restrict__ k,
                       const float* __restrict__ v) {
    const int N4 = BH * S * D / 4;
    int i = blockIdx.x * blockDim.x + threadIdx.x;
    if (i >= N4) return;
    float4 a = ((const float4*)q)[i];
    float4 b = ((const float4*)k)[i];
    float4 c = ((const float4*)v)[i];
    __half2* q2 = (__half2*)g_q16;
    __half2* k2 = (__half2*)g_k16;
    __half2* v2 = (__half2*)g_v16;
    q2[2 * i]     = __floats2half2_rn(a.x * INV_T, a.y * INV_T);
    q2[2 * i + 1] = __floats2half2_rn(a.z * INV_T, a.w * INV_T);
    k2[2 * i]     = __floats2half2_rn(b.x, b.y);
    k2[2 * i + 1] = __floats2half2_rn(b.z, b.w);
    v2[2 * i]     = __floats2half2_rn(c.x, c.y);
    v2[2 * i + 1] = __floats2half2_rn(c.z, c.w);
}

// ---------------- main fused attention ----------------
__global__ __launch_bounds__(THREADS, 3)
void attn_main(const int* __restrict__ mask,
               float* __restrict__ out, float* __restrict__ attn)
{
    extern __shared__ char smem[];
    const uint32_t sb = su32(smem);
    const int tid = threadIdx.x;
    const int w   = tid >> 5;
    const int L   = tid & 31;
    const int q_  = L & 3;
    const int bh  = blockIdx.y;
    const int q0  = blockIdx.x * QT;

    const __half* qg = g_q16 + ((size_t)bh * S + q0) * D;
    const __half* kg = g_k16 + (size_t)bh * S * D;
    const __half* vg = g_v16 + (size_t)bh * S * D;

    const uint32_t sQ = sb + SM_Q;
    const uint32_t sK[2] = { sb + SM_K0, sb + SM_K1 };
    const uint32_t sV[2] = { sb + SM_V0, sb + SM_V1 };
    float* mf   = (float*)(smem + SM_MASK);
    float* sInv = (float*)(smem + SM_INV);

    load_q(sQ, qg, tid);
    load_t64(sK[0], kg, tid);
    load_t64(sV[0], vg, tid);
    CP_COMMIT();
    {
        const int* mp = mask + (size_t)(bh >> 4) * S;
        for (int i = tid; i < S; i += THREADS) mf[i] = mp[i] ? 1.0f : 0.0f;
    }
    CP_WAIT0();
    __syncthreads();

    const uint32_t q_part  = ((L & 7) + ((L >> 3) & 1) * 8) * RSB + (L >> 4) * 16;
    const uint32_t ka_part = (L & 7) * RSB + (L >> 3) * 16;
    const uint32_t va_part = L * RSB;
    const int      c_base  = 2 * q_;

    uint32_t qa[4][4];
    {
        const uint32_t qbase = sQ + w * 16 * RSB + q_part;
#pragma unroll
        for (int ks = 0; ks < 4; ks++)
            LDSM4(qa[ks][0], qa[ks][1], qa[ks][2], qa[ks][3], qbase + ks * 32);
    }

    float inv_lo, inv_hi;

    // ===== pass 1: QK + exp + sums + PV =====
    {
        float4 oc[8];
#pragma unroll
        for (int nb = 0; nb < 8; nb++) oc[nb] = make_float4(0.f, 0.f, 0.f, 0.f);
        float sum_lo = 0.0f, sum_hi = 0.0f;

        for (int kt = 0; kt < NTILES; kt++) {
            const int cur = kt & 1;
            if (kt + 1 < NTILES) {
                load_t64(sK[cur ^ 1], kg + (size_t)(kt + 1) * NT * D, tid);
                load_t64(sV[cur ^ 1], vg + (size_t)(kt + 1) * NT * D, tid);
                CP_COMMIT();
            }
            const float* mrow = mf + kt * NT;

#pragma unroll
            for (int kb2 = 0; kb2 < 2; kb2++) {
                uint32_t a16[2][4];
#pragma unroll
                for (int i = 0; i < 4; i++) {
                    int nb = kb2 * 4 + i;
                    uint32_t kaddr = sK[cur] + nb * 8 * RSB + ka_part;
                    uint32_t b0, b1, b2, b3, b4, b5, b6, b7;
                    LDSM4(b0, b1, b2, b3, kaddr);
                    LDSM4(b4, b5, b6, b7, kaddr + 64);
                    float4 cf = make_float4(0.f, 0.f, 0.f, 0.f);
                    mma_f16(cf, qa[0][0], qa[0][1], qa[0][2], qa[0][3], b0, b1);
                    mma_f16(cf, qa[1][0], qa[1][1], qa[1][2], qa[1][3], b2, b3);
                    mma_f16(cf, qa[2][0], qa[2][1], qa[2][2], qa[2][3], b4, b5);
                    mma_f16(cf, qa[3][0], qa[3][1], qa[3][2], qa[3][3], b6, b7);
                    int c0 = nb * 8 + c_base;
                    float m0 = mrow[c0], m1 = mrow[c0 + 1];
                    float e0 = __expf(cf.x) * m0;
                    float e1 = __expf(cf.y) * m1;
                    float e2 = __expf(cf.z) * m0;
                    float e3 = __expf(cf.w) * m1;
                    sum_lo += e0 + e1;
                    sum_hi += e2 + e3;
                    a16[i >> 1][(i & 1) * 2]     = packh2(e0, e1);
                    a16[i >> 1][(i & 1) * 2 + 1] = packh2(e2, e3);
                }
#pragma unroll
                for (int nbo = 0; nbo < 8; nbo++) {
                    uint32_t vaddr = sV[cur] + kb2 * 32 * RSB + nbo * 16 + va_part;
                    uint32_t v0, v1, v2, v3;
                    LDSM4T(v0, v1, v2, v3, vaddr);
                    mma_f16(oc[nbo], a16[0][0], a16[0][1], a16[0][2], a16[0][3], v0, v1);
                    mma_f16(oc[nbo], a16[1][0], a16[1][1], a16[1][2], a16[1][3], v2, v3);
                }
            }

            if (kt + 1 < NTILES) CP_WAIT0();
            __syncthreads();
        }

#pragma unroll
        for (int m = 1; m < 4; m <<= 1) {
            sum_lo += __shfl_xor_sync(0xffffffffu, sum_lo, m);
            sum_hi += __shfl_xor_sync(0xffffffffu, sum_hi, m);
        }
        inv_lo = 1.0f / sum_lo;
        inv_hi = 1.0f / sum_hi;

        if (q_ == 0) {
            sInv[w * 16 + (L >> 2)]     = inv_lo;
            sInv[w * 16 + 8 + (L >> 2)] = inv_hi;
        }

        float* olo = out + ((size_t)bh * S + q0 + w * 16 + (L >> 2)) * D + c_base;
        float* ohi = olo + 8 * D;
#pragma unroll
        for (int nb = 0; nb < 8; nb++) {
            *(float2*)(olo + nb * 8) = make_float2(oc[nb].x * inv_lo, oc[nb].y * inv_lo);
            *(float2*)(ohi + nb * 8) = make_float2(oc[nb].z * inv_hi, oc[nb].w * inv_hi);
        }
    }
    __syncthreads();

    // ===== pass 2: attn write only (QK recompute + exp + stcs) =====
    {
        float* arow_lo = attn + ((size_t)bh * S + q0 + w * 16 + (L >> 2)) * S;
        float* arow_hi = arow_lo + 8 * (size_t)S;

        load_t64(sK[0], kg, tid);
        CP_COMMIT();
        CP_WAIT0();
        __syncthreads();

        for (int kt = 0; kt < NTILES; kt++) {
            const int cur = kt & 1;
            if (kt + 1 < NTILES) {
                load_t64(sK[cur ^ 1], kg + (size_t)(kt + 1) * NT * D, tid);
                CP_COMMIT();
            }
            const float* mrow = mf + kt * NT;

#pragma unroll
            for (int kb2 = 0; kb2 < 2; kb2++) {
                float4 cf[4];
#pragma unroll
                for (int i = 0; i < 4; i++) {
                    int nb = kb2 * 4 + i;
                    uint32_t kaddr = sK[cur] + nb * 8 * RSB + ka_part;
                    uint32_t b0, b1, b2, b3, b4, b5, b6, b7;
                    LDSM4(b0, b1, b2, b3, kaddr);
                    LDSM4(b4, b5, b6, b7, kaddr + 64);
                    cf[i] = make_float4(0.f, 0.f, 0.f, 0.f);
                    mma_f16(cf[i], qa[0][0], qa[0][1], qa[0][2], qa[0][3], b0, b1);
                    mma_f16(cf[i], qa[1][0], qa[1][1], qa[1][2], qa[1][3], b2, b3);
                    mma_f16(cf[i], qa[2][0], qa[2][1], qa[2][2], qa[2][3], b4, b5);
                    mma_f16(cf[i], qa[3][0], qa[3][1], qa[3][2], qa[3][3], b6, b7);
                }
                float2 flo[4], fhi[4];
#pragma unroll
                for (int i = 0; i < 4; i++) {
                    int c0 = (kb2 * 4 + i) * 8 + c_base;
                    float m0 = mrow[c0], m1 = mrow[c0 + 1];
                    flo[i] = make_float2(__expf(cf[i].x) * m0 * inv_lo,
                                         __expf(cf[i].y) * m1 * inv_lo);
                    fhi[i] = make_float2(__expf(cf[i].z) * m0 * inv_hi,
                                         __expf(cf[i].w) * m1 * inv_hi);
                }
                quad_transpose_f2(flo, q_);
                quad_transpose_f2(fhi, q_);
                int col = kt * NT + kb2 * 32 + 8 * q_;
                __stcs((float4*)(arow_lo + col),
                       make_float4(flo[0].x, flo[0].y, flo[1].x, flo[1].y));
                __stcs((float4*)(arow_lo + col + 4),
                       make_float4(flo[2].x, flo[2].y, flo[3].x, flo[3].y));
                __stcs((float4*)(arow_hi + col),
                       make_float4(fhi[0].x, fhi[0].y, fhi[1].x, fhi[1].y));
                __stcs((float4*)(arow_hi + col + 4),
                       make_float4(fhi[2].x, fhi[2].y, fhi[3].x, fhi[3].y));
            }

            if (kt + 1 < NTILES) CP_WAIT0();
            __syncthreads();
        }
    }
}

// ---------------- launch ----------------
extern "C" void kernel_launch(void* const* d_in, const int* in_sizes, int n_in,
                              void* d_out, int out_size)
{
    const float* q    = (const float*)d_in[0];
    const float* k    = (const float*)d_in[1];
    const float* v    = (const float*)d_in[2];
    const int*   mask = (const int*)  d_in[3];

    float* out  = (float*)d_out;
    float* attn = out + (size_t)BH * S * D;

    cudaFuncSetAttribute(attn_main, cudaFuncAttributeMaxDynamicSharedMemorySize, SMEM_SZ);

    const int N4 = BH * S * D / 4;
    prep16<<<(N4 + 255) / 256, 256>>>(q, k, v);
    attn_main<<<dim3(S / QT, BH), THREADS, SMEM_SZ>>>(mask, out, attn);
}

// round 9
// speedup vs baseline: 1.1900x; 1.1900x over previous
#include <cuda_runtime.h>
#include <cuda_fp16.h>
#include <stdint.h>

// ---------------- problem constants ----------------
constexpr int B = 2, H = 16, S = 2048, D = 64;
constexpr int BH = B * H;
constexpr float INV_T = 1.0f / 32.0f;

constexpr int QT = 256;           // query rows per CTA (two 128-row halves A,B)
constexpr int NT = 128;           // keys per tile
constexpr int NTILES = S / NT;    // 16
constexpr int THREADS = 256;      // 8 warps; warp w owns rows 16w..16w+15 of each half

// smem: rows of 64 fp16 padded to 72 (144B) -> conflict-free ldmatrix
constexpr int RSB = 144;
constexpr int TILE_BYTES = 128 * RSB;   // 18432

constexpr int SM_Q    = 0;                       // QA then QB (reused)
constexpr int SM_K0   = SM_Q  + TILE_BYTES;
constexpr int SM_K1   = SM_K0 + TILE_BYTES;
constexpr int SM_V0   = SM_K1 + TILE_BYTES;
constexpr int SM_V1   = SM_V0 + TILE_BYTES;
constexpr int SM_MASK = SM_V1 + TILE_BYTES;      // 2048 floats
constexpr int SM_INV  = SM_MASK + S * 4;         // 128 floats (for B half)
constexpr int SMEM_SZ = SM_INV + 512;            // 100864 B -> 2 CTAs/SM

// ---------------- device fp16 copies ----------------
__device__ __half g_q16[(size_t)BH * S * D];
__device__ __half g_k16[(size_t)BH * S * D];
__device__ __half g_v16[(size_t)BH * S * D];

// ---------------- helpers ----------------
__device__ __forceinline__ uint32_t su32(const void* p) {
    uint32_t a;
    asm("{ .reg .u64 t; cvta.to.shared.u64 t, %1; cvt.u32.u64 %0, t; }" : "=r"(a) : "l"(p));
    return a;
}
__device__ __forceinline__ void cpa16(uint32_t d, const void* s) {
    asm volatile("cp.async.cg.shared.global [%0], [%1], 16;" :: "r"(d), "l"(s));
}
#define CP_COMMIT() asm volatile("cp.async.commit_group;" ::: "memory")
#define CP_WAIT0()  asm volatile("cp.async.wait_group 0;" ::: "memory")
#define BARG(id)    asm volatile("bar.sync %0, 128;" :: "r"(id) : "memory")

#define LDSM4(r0, r1, r2, r3, a) \
    asm volatile("ldmatrix.sync.aligned.m8n8.x4.shared.b16 {%0,%1,%2,%3}, [%4];" \
                 : "=r"(r0), "=r"(r1), "=r"(r2), "=r"(r3) : "r"(a))
#define LDSM4T(r0, r1, r2, r3, a) \
    asm volatile("ldmatrix.sync.aligned.m8n8.x4.trans.shared.b16 {%0,%1,%2,%3}, [%4];" \
                 : "=r"(r0), "=r"(r1), "=r"(r2), "=r"(r3) : "r"(a))

__device__ __forceinline__ void mma_f16(float4& c, const uint32_t a[4],
                                        uint32_t b0, uint32_t b1) {
    asm volatile(
        "mma.sync.aligned.m16n8k16.row.col.f32.f16.f16.f32 "
        "{%0,%1,%2,%3}, {%4,%5,%6,%7}, {%8,%9}, {%0,%1,%2,%3};"
        : "+f"(c.x), "+f"(c.y), "+f"(c.z), "+f"(c.w)
        : "r"(a[0]), "r"(a[1]), "r"(a[2]), "r"(a[3]), "r"(b0), "r"(b1));
}
__device__ __forceinline__ uint32_t packh2(float a, float b) {
    __half2 h = __floats2half2_rn(a, b);
    return *(uint32_t*)&h;
}
__device__ __forceinline__ float2 shfl_xor_f2(float2 v, int m) {
    v.x = __shfl_xor_sync(0xffffffffu, v.x, m);
    v.y = __shfl_xor_sync(0xffffffffu, v.y, m);
    return v;
}
__device__ __forceinline__ void quad_transpose_f2(float2 a[4], int q) {
    {
        float2 v = (q & 1) ? a[0] : a[1];
        v = shfl_xor_f2(v, 1);
        if (q & 1) a[0] = v; else a[1] = v;
        float2 u = (q & 1) ? a[2] : a[3];
        u = shfl_xor_f2(u, 1);
        if (q & 1) a[2] = u; else a[3] = u;
    }
    {
        float2 v = (q & 2) ? a[0] : a[2];
        v = shfl_xor_f2(v, 2);
        if (q & 2) a[0] = v; else a[2] = v;
        float2 u = (q & 2) ? a[1] : a[3];
        u = shfl_xor_f2(u, 2);
        if (q & 2) a[1] = u; else a[3] = u;
    }
}

// 128-row tile -> padded smem (256 threads)
__device__ __forceinline__ void load_tile(uint32_t sdst, const __half* g, int tid) {
#pragma unroll
    for (int it = 0; it < 4; it++) {
        int f = tid + it * THREADS;
        int r = f >> 3, c = f & 7;
        cpa16(sdst + r * RSB + c * 16, g + r * 64 + c * 8);
    }
}
// 128-thread group tile load (pass2 parity)
__device__ __forceinline__ void load_tile_g(uint32_t sdst, const __half* g, int gtid) {
#pragma unroll
    for (int it = 0; it < 8; it++) {
        int f = gtid + it * 128;
        int r = f >> 3, c = f & 7;
        cpa16(sdst + r * RSB + c * 16, g + r * 64 + c * 8);
    }
}

// ---------------- prep: fp32 -> fp16 (Q scaled by 1/T) ----------------
__global__ void prep16(const float* __restrict__ q, const float* __restrict__ k,
                       const float* __restrict__ v) {
    const int N4 = BH * S * D / 4;
    int i = blockIdx.x * blockDim.x + threadIdx.x;
    if (i >= N4) return;
    float4 a = ((const float4*)q)[i];
    float4 b = ((const float4*)k)[i];
    float4 c = ((const float4*)v)[i];
    __half2* q2 = (__half2*)g_q16;
    __half2* k2 = (__half2*)g_k16;
    __half2* v2 = (__half2*)g_v16;
    q2[2 * i]     = __floats2half2_rn(a.x * INV_T, a.y * INV_T);
    q2[2 * i + 1] = __floats2half2_rn(a.z * INV_T, a.w * INV_T);
    k2[2 * i]     = __floats2half2_rn(b.x, b.y);
    k2[2 * i + 1] = __floats2half2_rn(b.z, b.w);
    v2[2 * i]     = __floats2half2_rn(c.x, c.y);
    v2[2 * i + 1] = __floats2half2_rn(c.z, c.w);
}

// ---------------- main fused attention ----------------
__global__ __launch_bounds__(THREADS, 2)
void attn_main(const int* __restrict__ mask,
               float* __restrict__ out, float* __restrict__ attn)
{
    extern __shared__ char smem[];
    const uint32_t sb = su32(smem);
    const int tid = threadIdx.x;
    const int w   = tid >> 5;
    const int L   = tid & 31;
    const int q_  = L & 3;
    const int bh  = blockIdx.y;
    const int q0  = blockIdx.x * QT;      // A half rows q0.., B half rows q0+128..

    const __half* qgA = g_q16 + ((size_t)bh * S + q0) * D;
    const __half* qgB = qgA + 128 * D;
    const __half* kg  = g_k16 + (size_t)bh * S * D;
    const __half* vg  = g_v16 + (size_t)bh * S * D;

    const uint32_t sQ = sb + SM_Q;
    const uint32_t sK[2] = { sb + SM_K0, sb + SM_K1 };
    const uint32_t sV[2] = { sb + SM_V0, sb + SM_V1 };
    float* mf   = (float*)(smem + SM_MASK);
    float* sInv = (float*)(smem + SM_INV);

    // prologue: QA + first K/V tile + mask
    load_tile(sQ, qgA, tid);
    load_tile(sK[0], kg, tid);
    load_tile(sV[0], vg, tid);
    CP_COMMIT();
    {
        const int* mp = mask + (size_t)(bh >> 4) * S;
        for (int i = tid; i < S; i += THREADS) mf[i] = mp[i] ? 1.0f : 0.0f;
    }
    CP_WAIT0();
    __syncthreads();

    const uint32_t q_part  = ((L & 7) + ((L >> 3) & 1) * 8) * RSB + (L >> 4) * 16;
    const uint32_t ka_part = (L & 7) * RSB + (L >> 3) * 16;
    const uint32_t va_part = L * RSB;
    const int      c_base  = 2 * q_;

    uint32_t qaA[4][4];
    {
        const uint32_t qb = sQ + w * 16 * RSB + q_part;
#pragma unroll
        for (int ks = 0; ks < 4; ks++)
            LDSM4(qaA[ks][0], qaA[ks][1], qaA[ks][2], qaA[ks][3], qb + ks * 32);
    }
    __syncthreads();   // all warps done reading QA -> region reusable for QB

    float invA_lo, invA_hi;

    // ===== loop 1: pass1(A): QK_A + exp + sums + PV_A =====
    {
        float4 oc[8];
#pragma unroll
        for (int nb = 0; nb < 8; nb++) oc[nb] = make_float4(0.f, 0.f, 0.f, 0.f);
        float sum_lo = 0.0f, sum_hi = 0.0f;

        for (int kt = 0; kt < NTILES; kt++) {
            const int cur = kt & 1;
            if (kt + 1 < NTILES) {
                load_tile(sK[cur ^ 1], kg + (size_t)(kt + 1) * NT * D, tid);
                load_tile(sV[cur ^ 1], vg + (size_t)(kt + 1) * NT * D, tid);
                if (kt == 0) load_tile(sQ, qgB, tid);   // QB rides along
                CP_COMMIT();
            }
            const float* mrow = mf + kt * NT;

#pragma unroll
            for (int kb2 = 0; kb2 < 4; kb2++) {
                uint32_t a16[2][4];
#pragma unroll
                for (int i = 0; i < 4; i++) {
                    int nb = kb2 * 4 + i;
                    uint32_t kaddr = sK[cur] + nb * 8 * RSB + ka_part;
                    uint32_t b0, b1, b2, b3, b4, b5, b6, b7;
                    LDSM4(b0, b1, b2, b3, kaddr);
                    LDSM4(b4, b5, b6, b7, kaddr + 64);
                    float4 cf = make_float4(0.f, 0.f, 0.f, 0.f);
                    mma_f16(cf, qaA[0], b0, b1);
                    mma_f16(cf, qaA[1], b2, b3);
                    mma_f16(cf, qaA[2], b4, b5);
                    mma_f16(cf, qaA[3], b6, b7);
                    int c0 = nb * 8 + c_base;
                    float m0 = mrow[c0], m1 = mrow[c0 + 1];
                    float e0 = __expf(cf.x) * m0;
                    float e1 = __expf(cf.y) * m1;
                    float e2 = __expf(cf.z) * m0;
                    float e3 = __expf(cf.w) * m1;
                    sum_lo += e0 + e1;
                    sum_hi += e2 + e3;
                    a16[i >> 1][(i & 1) * 2]     = packh2(e0, e1);
                    a16[i >> 1][(i & 1) * 2 + 1] = packh2(e2, e3);
                }
#pragma unroll
                for (int nbo = 0; nbo < 8; nbo++) {
                    uint32_t vaddr = sV[cur] + kb2 * 32 * RSB + nbo * 16 + va_part;
                    uint32_t v0, v1, v2, v3;
                    LDSM4T(v0, v1, v2, v3, vaddr);
                    mma_f16(oc[nbo], a16[0], v0, v1);
                    mma_f16(oc[nbo], a16[1], v2, v3);
                }
            }

            if (kt + 1 < NTILES) CP_WAIT0();
            __syncthreads();
        }

#pragma unroll
        for (int m = 1; m < 4; m <<= 1) {
            sum_lo += __shfl_xor_sync(0xffffffffu, sum_lo, m);
            sum_hi += __shfl_xor_sync(0xffffffffu, sum_hi, m);
        }
        invA_lo = 1.0f / sum_lo;
        invA_hi = 1.0f / sum_hi;

        float* olo = out + ((size_t)bh * S + q0 + w * 16 + (L >> 2)) * D + c_base;
        float* ohi = olo + 8 * D;
#pragma unroll
        for (int nb = 0; nb < 8; nb++) {
            *(float2*)(olo + nb * 8) = make_float2(oc[nb].x * invA_lo, oc[nb].y * invA_lo);
            *(float2*)(ohi + nb * 8) = make_float2(oc[nb].z * invA_hi, oc[nb].w * invA_hi);
        }
    }

    // QB fragments (QB load completed long ago inside loop1's group stream)
    uint32_t qaB[4][4];
    {
        const uint32_t qb = sQ + w * 16 * RSB + q_part;
#pragma unroll
        for (int ks = 0; ks < 4; ks++)
            LDSM4(qaB[ks][0], qaB[ks][1], qaB[ks][2], qaB[ks][3], qb + ks * 32);
    }

    // ===== loop 2: fused attnA write + pass1(B); shared K LDSM =====
    float invB_lo, invB_hi;
    {
        load_tile(sK[0], kg, tid);
        load_tile(sV[0], vg, tid);
        CP_COMMIT();
        CP_WAIT0();
        __syncthreads();

        float4 oc[8];
#pragma unroll
        for (int nb = 0; nb < 8; nb++) oc[nb] = make_float4(0.f, 0.f, 0.f, 0.f);
        float sum_lo = 0.0f, sum_hi = 0.0f;

        float* arow_lo = attn + ((size_t)bh * S + q0 + w * 16 + (L >> 2)) * S;
        float* arow_hi = arow_lo + 8 * (size_t)S;

        for (int kt = 0; kt < NTILES; kt++) {
            const int cur = kt & 1;
            if (kt + 1 < NTILES) {
                load_tile(sK[cur ^ 1], kg + (size_t)(kt + 1) * NT * D, tid);
                load_tile(sV[cur ^ 1], vg + (size_t)(kt + 1) * NT * D, tid);
                CP_COMMIT();
            }
            const float* mrow = mf + kt * NT;

#pragma unroll
            for (int kb2 = 0; kb2 < 4; kb2++) {
                float4 cfA[4];
                uint32_t a16[2][4];
#pragma unroll
                for (int i = 0; i < 4; i++) {
                    int nb = kb2 * 4 + i;
                    uint32_t kaddr = sK[cur] + nb * 8 * RSB + ka_part;
                    uint32_t b0, b1, b2, b3, b4, b5, b6, b7;
                    LDSM4(b0, b1, b2, b3, kaddr);
                    LDSM4(b4, b5, b6, b7, kaddr + 64);
                    // QK for A (attn recompute) — shares the B-operand regs
                    cfA[i] = make_float4(0.f, 0.f, 0.f, 0.f);
                    mma_f16(cfA[i], qaA[0], b0, b1);
                    mma_f16(cfA[i], qaA[1], b2, b3);
                    mma_f16(cfA[i], qaA[2], b4, b5);
                    mma_f16(cfA[i], qaA[3], b6, b7);
                    // QK for B (pass1)
                    float4 cfB = make_float4(0.f, 0.f, 0.f, 0.f);
                    mma_f16(cfB, qaB[0], b0, b1);
                    mma_f16(cfB, qaB[1], b2, b3);
                    mma_f16(cfB, qaB[2], b4, b5);
                    mma_f16(cfB, qaB[3], b6, b7);
                    int c0 = nb * 8 + c_base;
                    float m0 = mrow[c0], m1 = mrow[c0 + 1];
                    float e0 = __expf(cfB.x) * m0;
                    float e1 = __expf(cfB.y) * m1;
                    float e2 = __expf(cfB.z) * m0;
                    float e3 = __expf(cfB.w) * m1;
                    sum_lo += e0 + e1;
                    sum_hi += e2 + e3;
                    a16[i >> 1][(i & 1) * 2]     = packh2(e0, e1);
                    a16[i >> 1][(i & 1) * 2 + 1] = packh2(e2, e3);
                }
                // attn_A write for these 32 keys
                {
                    float2 flo[4], fhi[4];
#pragma unroll
                    for (int i = 0; i < 4; i++) {
                        int c0 = (kb2 * 4 + i) * 8 + c_base;
                        float m0 = mrow[c0], m1 = mrow[c0 + 1];
                        flo[i] = make_float2(__expf(cfA[i].x) * m0 * invA_lo,
                                             __expf(cfA[i].y) * m1 * invA_lo);
                        fhi[i] = make_float2(__expf(cfA[i].z) * m0 * invA_hi,
                                             __expf(cfA[i].w) * m1 * invA_hi);
                    }
                    quad_transpose_f2(flo, q_);
                    quad_transpose_f2(fhi, q_);
                    int col = kt * NT + kb2 * 32 + 8 * q_;
                    __stcs((float4*)(arow_lo + col),
                           make_float4(flo[0].x, flo[0].y, flo[1].x, flo[1].y));
                    __stcs((float4*)(arow_lo + col + 4),
                           make_float4(flo[2].x, flo[2].y, flo[3].x, flo[3].y));
                    __stcs((float4*)(arow_hi + col),
                           make_float4(fhi[0].x, fhi[0].y, fhi[1].x, fhi[1].y));
                    __stcs((float4*)(arow_hi + col + 4),
                           make_float4(fhi[2].x, fhi[2].y, fhi[3].x, fhi[3].y));
                }
                // PV for B
#pragma unroll
                for (int nbo = 0; nbo < 8; nbo++) {
                    uint32_t vaddr = sV[cur] + kb2 * 32 * RSB + nbo * 16 + va_part;
                    uint32_t v0, v1, v2, v3;
                    LDSM4T(v0, v1, v2, v3, vaddr);
                    mma_f16(oc[nbo], a16[0], v0, v1);
                    mma_f16(oc[nbo], a16[1], v2, v3);
                }
            }

            if (kt + 1 < NTILES) CP_WAIT0();
            __syncthreads();
        }

#pragma unroll
        for (int m = 1; m < 4; m <<= 1) {
            sum_lo += __shfl_xor_sync(0xffffffffu, sum_lo, m);
            sum_hi += __shfl_xor_sync(0xffffffffu, sum_hi, m);
        }
        invB_lo = 1.0f / sum_lo;
        invB_hi = 1.0f / sum_hi;

        if (q_ == 0) {
            sInv[w * 16 + (L >> 2)]     = invB_lo;
            sInv[w * 16 + 8 + (L >> 2)] = invB_hi;
        }

        float* olo = out + ((size_t)bh * S + q0 + 128 + w * 16 + (L >> 2)) * D + c_base;
        float* ohi = olo + 8 * D;
#pragma unroll
        for (int nb = 0; nb < 8; nb++) {
            *(float2*)(olo + nb * 8) = make_float2(oc[nb].x * invB_lo, oc[nb].y * invB_lo);
            *(float2*)(ohi + nb * 8) = make_float2(oc[nb].z * invB_hi, oc[nb].w * invB_hi);
        }
    }
    __syncthreads();   // sInv visible; all buffers free

    // ===== loop 3: attn_B write (tile-parity split groups, 32 rows/warp) =====
    {
        const int p    = w >> 2;
        const int g    = w & 3;
        const int gtid = tid & 127;
        const int bar  = 1 + p;
        const uint32_t bufs[2] = { p ? sV[0] : sK[0], p ? sV[1] : sK[1] };

        uint32_t qa2[2][4][4];
#pragma unroll
        for (int mb = 0; mb < 2; mb++) {
            const uint32_t qb = sQ + (g * 32 + mb * 16) * RSB + q_part;
#pragma unroll
            for (int ks = 0; ks < 4; ks++)
                LDSM4(qa2[mb][ks][0], qa2[mb][ks][1], qa2[mb][ks][2], qa2[mb][ks][3],
                      qb + ks * 32);
        }

        float invA2[2], invB2[2];
#pragma unroll
        for (int mb = 0; mb < 2; mb++) {
            invA2[mb] = sInv[g * 32 + mb * 16 + (L >> 2)];
            invB2[mb] = sInv[g * 32 + mb * 16 + 8 + (L >> 2)];
        }
        float* arow0[2];
#pragma unroll
        for (int mb = 0; mb < 2; mb++)
            arow0[mb] = attn + ((size_t)bh * S + q0 + 128 + g * 32 + mb * 16 + (L >> 2)) * S;

        load_tile_g(bufs[0], kg + (size_t)p * NT * D, gtid);
        CP_COMMIT();
        CP_WAIT0();
        BARG(bar);

        for (int i = 0; i < 8; i++) {
            const int kt  = p + 2 * i;
            const int cur = i & 1;
            if (i + 1 < 8) {
                load_tile_g(bufs[cur ^ 1], kg + (size_t)(kt + 2) * NT * D, gtid);
                CP_COMMIT();
            }
            const float* mrow = mf + kt * NT;

#pragma unroll
            for (int kb2 = 0; kb2 < 4; kb2++) {
                float4 cf[2][4];
#pragma unroll
                for (int i4 = 0; i4 < 4; i4++) {
                    int nb = kb2 * 4 + i4;
                    uint32_t kaddr = bufs[cur] + nb * 8 * RSB + ka_part;
                    uint32_t b0, b1, b2, b3, b4, b5, b6, b7;
                    LDSM4(b0, b1, b2, b3, kaddr);
                    LDSM4(b4, b5, b6, b7, kaddr + 64);
#pragma unroll
                    for (int mb = 0; mb < 2; mb++) {
                        cf[mb][i4] = make_float4(0.f, 0.f, 0.f, 0.f);
                        mma_f16(cf[mb][i4], qa2[mb][0], b0, b1);
                        mma_f16(cf[mb][i4], qa2[mb][1], b2, b3);
                        mma_f16(cf[mb][i4], qa2[mb][2], b4, b5);
                        mma_f16(cf[mb][i4], qa2[mb][3], b6, b7);
                    }
                }
#pragma unroll
                for (int mb = 0; mb < 2; mb++) {
                    float2 flo[4], fhi[4];
#pragma unroll
                    for (int i4 = 0; i4 < 4; i4++) {
                        int c0 = (kb2 * 4 + i4) * 8 + c_base;
                        float m0 = mrow[c0], m1 = mrow[c0 + 1];
                        flo[i4] = make_float2(__expf(cf[mb][i4].x) * m0 * invA2[mb],
                                              __expf(cf[mb][i4].y) * m1 * invA2[mb]);
                        fhi[i4] = make_float2(__expf(cf[mb][i4].z) * m0 * invB2[mb],
                                              __expf(cf[mb][i4].w) * m1 * invB2[mb]);
                    }
                    quad_transpose_f2(flo, q_);
                    quad_transpose_f2(fhi, q_);
                    int col = kt * NT + kb2 * 32 + 8 * q_;
                    float* alo = arow0[mb];
                    float* ahi = alo + 8 * (size_t)S;
                    __stcs((float4*)(alo + col),
                           make_float4(flo[0].x, flo[0].y, flo[1].x, flo[1].y));
                    __stcs((float4*)(alo + col + 4),
                           make_float4(flo[2].x, flo[2].y, flo[3].x, flo[3].y));
                    __stcs((float4*)(ahi + col),
                           make_float4(fhi[0].x, fhi[0].y, fhi[1].x, fhi[1].y));
                    __stcs((float4*)(ahi + col + 4),
                           make_float4(fhi[2].x, fhi[2].y, fhi[3].x, fhi[3].y));
                }
            }

            if (i + 1 < 8) CP_WAIT0();
            BARG(bar);
        }
    }
}

// ---------------- launch ----------------
extern "C" void kernel_launch(void* const* d_in, const int* in_sizes, int n_in,
                              void* d_out, int out_size)
{
    const float* q    = (const float*)d_in[0];
    const float* k    = (const float*)d_in[1];
    const float* v    = (const float*)d_in[2];
    const int*   mask = (const int*)  d_in[3];

    float* out  = (float*)d_out;
    float* attn = out + (size_t)BH * S * D;

    cudaFuncSetAttribute(attn_main, cudaFuncAttributeMaxDynamicSharedMemorySize, SMEM_SZ);

    const int N4 = BH * S * D / 4;
    prep16<<<(N4 + 255) / 256, 256>>>(q, k, v);
    attn_main<<<dim3(S / QT, BH), THREADS, SMEM_SZ>>>(mask, out, attn);
}